// round 14
// baseline (speedup 1.0000x reference)
#include <cuda_runtime.h>
#include <cstdint>

// MultiBackScatter: three chained scatter-adds with UNIQUE (permutation) indices.
// Composition: out[idx0[idx1[idx2[i]]]] = x[i]; all other rows zero.
//
// R14: 4-chunk cudaMemsetAsync (driver path, ~7.2TB/s measured in R13) with a
// forked side stream that (a) resolves the 3-level chase into g_tgt under
// chunk 0, and (b) scatters rows targeting chunk i as soon as chunk i's memset
// completes — overlapped with the remaining memsets (disjoint byte ranges).
// Only the last chunk's scatter (~6250 rows, chase-free) is serialized.
// Stream/events are created fresh per call (host-side only; kernel_launch runs
// only for correctness + capture). g_tgt writes are replay-idempotent.

#define N_SRC_MAX 25088

__device__ int g_tgt[N_SRC_MAX];   // composed output row per source row

__global__ void __launch_bounds__(256) prep_kernel(
        const int* __restrict__ idx0,
        const int* __restrict__ idx1,
        const int* __restrict__ idx2,
        int n_rows) {
    int i = blockIdx.x * 256 + threadIdx.x;
    if (i < n_rows) {
        int j = __ldg(&idx2[i]);
        int k = __ldg(&idx1[j]);
        g_tgt[i] = __ldg(&idx0[k]);
    }
}

// Scatter rows whose composed target lies in [lo_row, hi_row).
// 16 lanes per row; chase-free (g_tgt built by prep_kernel).
__global__ void __launch_bounds__(256) scatter_range_kernel(
        const float4* __restrict__ x,
        float4* __restrict__ out,
        int n_rows, int lo_row, int hi_row) {
    int t = blockIdx.x * 256 + threadIdx.x;
    int row = t >> 4;
    int lane = t & 15;
    if (row >= n_rows) return;
    int m = __ldg(&g_tgt[row]);                 // broadcast across 16 lanes
    if (m >= lo_row && m < hi_row) {
        out[(long long)m * 16 + lane] = __ldg(&x[(long long)row * 16 + lane]);
    }
}

extern "C" void kernel_launch(void* const* d_in, const int* in_sizes, int n_in,
                              void* d_out, int out_size) {
    const float* x   = (const float*)d_in[0];
    const int* idx0  = (const int*)d_in[1];
    const int* idx1  = (const int*)d_in[2];
    const int* idx2  = (const int*)d_in[3];
    float* out       = (float*)d_out;

    const int F = 64;
    int n_rows = in_sizes[0] / F;          // 25000
    int out_rows = out_size / F;           // 1600000
    const int NCHUNK = 4;
    int rows_per_chunk = out_rows / NCHUNK;              // 400000
    size_t bytes_per_chunk = (size_t)rows_per_chunk * F * sizeof(float);

    int scat_blocks = (n_rows * 16 + 255) / 256;         // 1563
    int prep_blocks = (n_rows + 255) / 256;              // 98

    // fresh fork stream + events each call (host objects only; ~2 calls total)
    cudaStream_t s2;
    cudaStreamCreateWithFlags(&s2, cudaStreamNonBlocking);
    cudaEvent_t e_fork, e_join;
    cudaEvent_t e_chunk[NCHUNK - 1];
    cudaEventCreateWithFlags(&e_fork, cudaEventDisableTiming);
    cudaEventCreateWithFlags(&e_join, cudaEventDisableTiming);
    for (int c = 0; c < NCHUNK - 1; c++)
        cudaEventCreateWithFlags(&e_chunk[c], cudaEventDisableTiming);

    // fork: side stream starts the chase immediately (independent of memsets)
    cudaEventRecord(e_fork, 0);
    cudaStreamWaitEvent(s2, e_fork, 0);
    prep_kernel<<<prep_blocks, 256, 0, s2>>>(idx0, idx1, idx2, n_rows);

    // main stream: chunked memsets; side stream scatters each finished chunk
    for (int c = 0; c < NCHUNK; c++) {
        cudaMemsetAsync((char*)out + (size_t)c * bytes_per_chunk, 0,
                        bytes_per_chunk, 0);
        if (c < NCHUNK - 1) {
            cudaEventRecord(e_chunk[c], 0);
            cudaStreamWaitEvent(s2, e_chunk[c], 0);
            scatter_range_kernel<<<scat_blocks, 256, 0, s2>>>(
                (const float4*)x, (float4*)out, n_rows,
                c * rows_per_chunk, (c + 1) * rows_per_chunk);
        }
    }

    // join side stream, then the only serialized piece: last chunk's scatter
    cudaEventRecord(e_join, s2);
    cudaStreamWaitEvent(0, e_join, 0);
    scatter_range_kernel<<<scat_blocks, 256>>>(
        (const float4*)x, (float4*)out, n_rows,
        (NCHUNK - 1) * rows_per_chunk, out_rows);
}

// round 15
// speedup vs baseline: 1.0882x; 1.0882x over previous
#include <cuda_runtime.h>
#include <cstdint>

// MultiBackScatter: three chained scatter-adds with UNIQUE (permutation) indices.
// Composition: out[idx0[idx1[idx2[i]]]] = x[i]; all other rows zero.
//
// R15: single cudaMemsetAsync node (driver zero-fill, ~7.2TB/s — R13/R14 showed
// chunking it is a net loss) + side-stream prep that resolves the 3-level index
// chase into g_tgt concurrently with the memset (touches only idx arrays, not
// out). The post-memset scatter is then chase-free (removes 3 dependent DRAM
// round-trips from the serialized tail; g_tgt/x lines arrive L2-warm).
// Stream/events are host-side objects created per call (no device allocation);
// g_tgt writes are replay-idempotent.

#define N_SRC_MAX 25088

__device__ int g_tgt[N_SRC_MAX];   // composed output row per source row

__global__ void __launch_bounds__(256) prep_kernel(
        const int* __restrict__ idx0,
        const int* __restrict__ idx1,
        const int* __restrict__ idx2,
        int n_rows) {
    int i = blockIdx.x * 256 + threadIdx.x;
    if (i < n_rows) {
        int j = __ldg(&idx2[i]);
        int k = __ldg(&idx1[j]);
        g_tgt[i] = __ldg(&idx0[k]);
    }
}

// Chase-free scatter: 16 lanes per row, one float4 per lane.
__global__ void __launch_bounds__(256) scatter_kernel(
        const float4* __restrict__ x,
        float4* __restrict__ out,
        int n_rows) {
    int t = blockIdx.x * 256 + threadIdx.x;
    int row = t >> 4;
    int lane = t & 15;
    if (row >= n_rows) return;
    int m = __ldg(&g_tgt[row]);                 // broadcast across 16 lanes, L2-warm
    out[(long long)m * 16 + lane] = __ldg(&x[(long long)row * 16 + lane]);
}

extern "C" void kernel_launch(void* const* d_in, const int* in_sizes, int n_in,
                              void* d_out, int out_size) {
    const float* x   = (const float*)d_in[0];
    const int* idx0  = (const int*)d_in[1];
    const int* idx1  = (const int*)d_in[2];
    const int* idx2  = (const int*)d_in[3];
    float* out       = (float*)d_out;

    const int F = 64;
    int n_rows = in_sizes[0] / F;            // 25000
    int prep_blocks = (n_rows + 255) / 256;  // 98
    int scat_blocks = (n_rows * 16 + 255) / 256;  // 1563

    // host-side stream/event objects (fresh per call; only ~2 calls happen)
    cudaStream_t s2;
    cudaStreamCreateWithFlags(&s2, cudaStreamNonBlocking);
    cudaEvent_t e_fork, e_join;
    cudaEventCreateWithFlags(&e_fork, cudaEventDisableTiming);
    cudaEventCreateWithFlags(&e_join, cudaEventDisableTiming);

    // fork: prep (index chase) runs concurrently with the memset
    cudaEventRecord(e_fork, 0);
    cudaStreamWaitEvent(s2, e_fork, 0);
    prep_kernel<<<prep_blocks, 256, 0, s2>>>(idx0, idx1, idx2, n_rows);
    cudaEventRecord(e_join, s2);

    // main stream: single full-size memset node (keep intact — 7.2TB/s)
    cudaMemsetAsync(d_out, 0, (size_t)out_size * sizeof(float), 0);

    // join, then the chase-free scatter tail
    cudaStreamWaitEvent(0, e_join, 0);
    scatter_kernel<<<scat_blocks, 256>>>((const float4*)x, (float4*)out, n_rows);
}

// round 16
// speedup vs baseline: 1.1081x; 1.0183x over previous
#include <cuda_runtime.h>
#include <cstdint>

// MultiBackScatter: three chained scatter-adds with UNIQUE (permutation) indices.
// Composition: out[idx0[idx1[idx2[i]]]] = x[i]; all other rows zero.
//
// R16: R13 structure (single-node driver memset at ~7.2TB/s + inline-chase
// scatter) but the memset is split into TWO CONCURRENT half-size nodes on two
// streams, probing copy-engine parallelism (if one memset node is CE-limited
// rather than DRAM-limited, two in parallel approach the HBM write wall).
// Minimal graph: 1 fork event + 1 join event; scatter identical to R13's
// proven 7.3us form.

__global__ void __launch_bounds__(256) scatter_kernel(
        const float4* __restrict__ x,
        const int* __restrict__ idx0,
        const int* __restrict__ idx1,
        const int* __restrict__ idx2,
        float4* __restrict__ out,
        int n_rows) {
    int t = blockIdx.x * 256 + threadIdx.x;
    int row = t >> 4;          // 16 lanes per row
    int lane = t & 15;
    if (row >= n_rows) return;

    // 3-level chase (broadcast across the 16 lanes; overlapped with x load)
    int j = __ldg(&idx2[row]);
    int k = __ldg(&idx1[j]);
    int m = __ldg(&idx0[k]);

    out[(long long)m * 16 + lane] = __ldg(&x[(long long)row * 16 + lane]);
}

extern "C" void kernel_launch(void* const* d_in, const int* in_sizes, int n_in,
                              void* d_out, int out_size) {
    const float* x   = (const float*)d_in[0];
    const int* idx0  = (const int*)d_in[1];
    const int* idx1  = (const int*)d_in[2];
    const int* idx2  = (const int*)d_in[3];
    float* out       = (float*)d_out;

    const int F = 64;
    int n_rows = in_sizes[0] / F;            // 25000
    size_t total_bytes = (size_t)out_size * sizeof(float);   // 409.6 MB
    size_t half = (total_bytes / 2) & ~(size_t)255;          // 256B-aligned split

    // host-side stream/events, fresh per call (no device allocation)
    cudaStream_t s2;
    cudaStreamCreateWithFlags(&s2, cudaStreamNonBlocking);
    cudaEvent_t e_fork, e_join;
    cudaEventCreateWithFlags(&e_fork, cudaEventDisableTiming);
    cudaEventCreateWithFlags(&e_join, cudaEventDisableTiming);

    // fork s2 from the capture stream
    cudaEventRecord(e_fork, 0);
    cudaStreamWaitEvent(s2, e_fork, 0);

    // two concurrent memset halves
    cudaMemsetAsync((char*)out, 0, half, 0);                       // main stream
    cudaMemsetAsync((char*)out + half, 0, total_bytes - half, s2); // side stream

    // join s2 back into the capture stream
    cudaEventRecord(e_join, s2);
    cudaStreamWaitEvent(0, e_join, 0);

    // scatter tail (R13 form: chase inline, 16 lanes per row)
    {
        int blocks = (n_rows * 16 + 255) / 256;   // 1563
        scatter_kernel<<<blocks, 256>>>((const float4*)x, idx0, idx1, idx2,
                                        (float4*)out, n_rows);
    }
}